// round 2
// baseline (speedup 1.0000x reference)
#include <cuda_runtime.h>

#define D       256
#define KCODES  1024
#define BM      128
#define BN      128
#define BD      32
#define LDA     129   // BM + 1 padding

// ---- scratch (no allocations allowed) ----
__device__ float  g_z_norm[131072];
__device__ float  g_e_half[KCODES];
__device__ float  g_counts[KCODES];
__device__ double g_loss;

// ---------------------------------------------------------------------------
__global__ void init_kernel() {
    int t = threadIdx.x;
    if (t < KCODES) g_counts[t] = 0.0f;
    if (t == 0)     g_loss = 0.0;
}

// One warp per row: ||z_n||^2 for n < N, 0.5*||e_k||^2 for the K codebook rows.
__global__ void norms_kernel(const float* __restrict__ z,
                             const float* __restrict__ e, int N) {
    int gw   = (blockIdx.x * blockDim.x + threadIdx.x) >> 5;
    int lane = threadIdx.x & 31;
    int total = N + KCODES;
    if (gw >= total) return;
    const float4* src = (const float4*)((gw < N) ? (z + (size_t)gw * D)
                                                 : (e + (size_t)(gw - N) * D));
    float4 a = src[lane];
    float4 b = src[lane + 32];
    float s = a.x*a.x + a.y*a.y + a.z*a.z + a.w*a.w
            + b.x*b.x + b.y*b.y + b.z*b.z + b.w*b.w;
    #pragma unroll
    for (int o = 16; o > 0; o >>= 1) s += __shfl_down_sync(0xffffffffu, s, o);
    if (lane == 0) {
        if (gw < N) g_z_norm[gw] = s;
        else        g_e_half[gw - N] = 0.5f * s;
    }
}

// ---------------------------------------------------------------------------
struct ComputeSmem {
    float As[BD][LDA];
    float Bs[BD][LDA];
    float eh[BN];
};
struct ReduceSmem {
    float rv[BM][16];
    int   ri[BM][16];
    float dv[BM];
    int   idx[BM];
};
union SmemU { ComputeSmem c; ReduceSmem r; };

// Block: 128 rows of z vs all 1024 codes. 256 threads (16x16), 8x8 micro-tile,
// stride-16 row/col mapping. Running argmin in registers, then gather.
__global__ __launch_bounds__(256) void vq_main(const float* __restrict__ z,
                                               const float* __restrict__ e,
                                               float* __restrict__ outq, int N) {
    __shared__ SmemU sm;
    const int tid = threadIdx.x;
    const int tx = tid & 15;
    const int ty = tid >> 4;
    const int rowbase = blockIdx.x * BM;

    float minv[8];
    int   mini[8];
    #pragma unroll
    for (int i = 0; i < 8; ++i) { minv[i] = __int_as_float(0x7f800000); mini[i] = 0; }

    #pragma unroll 1
    for (int kt = 0; kt < KCODES; kt += BN) {
        __syncthreads();                       // protect eh from previous epilogue
        if (tid < BN) sm.c.eh[tid] = g_e_half[kt + tid];

        float acc[8][8];
        #pragma unroll
        for (int i = 0; i < 8; ++i)
            #pragma unroll
            for (int j = 0; j < 8; ++j) acc[i][j] = 0.0f;

        #pragma unroll 1
        for (int d0 = 0; d0 < D; d0 += BD) {
            __syncthreads();
            // load A (z rows) and B (codes) chunks, transposed into SMEM
            #pragma unroll
            for (int it = 0; it < 4; ++it) {
                int id = tid + it * 256;
                int r  = id >> 3;          // 0..127
                int c4 = id & 7;           // 0..7  (float4 within 32-col chunk)
                float4 v = *(const float4*)(z + (size_t)(rowbase + r) * D + d0 + c4 * 4);
                sm.c.As[c4*4+0][r] = v.x;
                sm.c.As[c4*4+1][r] = v.y;
                sm.c.As[c4*4+2][r] = v.z;
                sm.c.As[c4*4+3][r] = v.w;
                float4 w = *(const float4*)(e + (size_t)(kt + r) * D + d0 + c4 * 4);
                sm.c.Bs[c4*4+0][r] = w.x;
                sm.c.Bs[c4*4+1][r] = w.y;
                sm.c.Bs[c4*4+2][r] = w.z;
                sm.c.Bs[c4*4+3][r] = w.w;
            }
            __syncthreads();

            #pragma unroll 8
            for (int kk = 0; kk < BD; ++kk) {
                float a[8], b[8];
                #pragma unroll
                for (int i = 0; i < 8; ++i) a[i] = sm.c.As[kk][ty + 16 * i];
                #pragma unroll
                for (int j = 0; j < 8; ++j) b[j] = sm.c.Bs[kk][tx + 16 * j];
                #pragma unroll
                for (int i = 0; i < 8; ++i)
                    #pragma unroll
                    for (int j = 0; j < 8; ++j)
                        acc[i][j] += a[i] * b[j];
            }
        }

        // epilogue: score = 0.5*||e||^2 - z.e ; update running argmin
        #pragma unroll
        for (int j = 0; j < 8; ++j) {
            float ehv = sm.c.eh[tx + 16 * j];
            int   col = kt + tx + 16 * j;
            #pragma unroll
            for (int i = 0; i < 8; ++i) {
                float s = ehv - acc[i][j];
                if (s < minv[i]) { minv[i] = s; mini[i] = col; }
            }
        }
    }

    __syncthreads();   // done with compute SMEM; switch union to reduce view
    #pragma unroll
    for (int i = 0; i < 8; ++i) {
        int r = ty + 16 * i;
        sm.r.rv[r][tx] = minv[i];
        sm.r.ri[r][tx] = mini[i];
    }
    __syncthreads();

    if (tid < BM) {
        float bv = sm.r.rv[tid][0];
        int   bi = sm.r.ri[tid][0];
        #pragma unroll
        for (int t = 1; t < 16; ++t) {
            float v  = sm.r.rv[tid][t];
            int   ix = sm.r.ri[tid][t];
            if (v < bv || (v == bv && ix < bi)) { bv = v; bi = ix; }
        }
        sm.r.idx[tid] = bi;
        sm.r.dv[tid]  = g_z_norm[rowbase + tid] + 2.0f * bv;  // ||z - e||^2
        atomicAdd(&g_counts[bi], 1.0f);
    }
    __syncthreads();

    // block loss reduction (128 values)
    if (tid < 64) sm.r.dv[tid] += sm.r.dv[tid + 64];
    __syncthreads();
    if (tid < 32) {
        float v = sm.r.dv[tid] + sm.r.dv[tid + 32];
        #pragma unroll
        for (int o = 16; o > 0; o >>= 1) v += __shfl_down_sync(0xffffffffu, v, o);
        if (tid == 0) atomicAdd(&g_loss, (double)v);
    }
    __syncthreads();

    // gather quantized rows to output (scalar stores: out base is +1 float,
    // so float4 would be misaligned; coalesced 32-bit stores are BW-full)
    #pragma unroll 1
    for (int p = tid; p < BM * D; p += 256) {
        int r = p >> 8;
        int c = p & 255;
        outq[(size_t)(rowbase + r) * D + c] = e[(size_t)sm.r.idx[r] * D + c];
    }
}

// ---------------------------------------------------------------------------
__global__ void finalize_kernel(float* __restrict__ out, int N) {
    __shared__ float red[1024];
    int t = threadIdx.x;
    float p = g_counts[t] * (1.0f / (float)N);
    red[t] = p * logf(p + 1e-10f);
    __syncthreads();
    for (int o = 512; o > 0; o >>= 1) {
        if (t < o) red[t] += red[t + o];
        __syncthreads();
    }
    if (t == 0) {
        out[0] = 0.25f * (float)(g_loss / ((double)N * (double)D));
        out[(size_t)N * D + 1] = expf(-red[0]);
    }
}

// ---------------------------------------------------------------------------
extern "C" void kernel_launch(void* const* d_in, const int* in_sizes, int n_in,
                              void* d_out, int out_size) {
    const float* z = (const float*)d_in[0];   // z_e  [N, 256]
    const float* e = (const float*)d_in[1];   // emb  [1024, 256]
    float* out = (float*)d_out;               // [loss, quantized(N*256), perplexity]
    int N = in_sizes[0] / D;                  // 131072

    init_kernel<<<1, 1024>>>();
    int warps  = N + KCODES;
    int blocks = (warps * 32 + 255) / 256;
    norms_kernel<<<blocks, 256>>>(z, e, N);
    vq_main<<<N / BM, 256>>>(z, e, out + 1, N);
    finalize_kernel<<<1, 1024>>>(out, N);
}

// round 5
// speedup vs baseline: 1.9794x; 1.9794x over previous
#include <cuda_runtime.h>
#include <cuda_bf16.h>
#include <cstdint>

#define D        256
#define KCODES   1024
#define BM       128
#define GAP_THRESH 0.001f
#define DYN_SMEM 172032   // 1KB align pad + sA 128KB + sB 32KB + eh 4KB + red 3KB

// ---- device scratch (no allocations allowed) ----
__device__ uint32_t g_epack[KCODES * 256];   // per code: [eh 128 u32 | el 128 u32] (bf16x2)
__device__ float    g_e_half[KCODES];
__device__ float    g_counts[KCODES];
__device__ int      g_idx[131072];
__device__ int      g_flag_rows[131072];
__device__ int      g_flag_cnt;
__device__ double   g_loss;

// ============================ helpers ============================
__device__ __forceinline__ uint32_t smem_u32(const void* p) {
    uint32_t a;
    asm("{ .reg .u64 t; cvta.to.shared.u64 t, %1; cvt.u32.u64 %0, t; }" : "=r"(a) : "l"(p));
    return a;
}

__device__ __forceinline__ void split2(float a, float b, uint32_t& hi, uint32_t& lo) {
    __nv_bfloat16 ha = __float2bfloat16(a);
    __nv_bfloat16 hb = __float2bfloat16(b);
    float ra = a - __bfloat162float(ha);
    float rb = b - __bfloat162float(hb);
    __nv_bfloat162 h = __halves2bfloat162(ha, hb);
    __nv_bfloat162 l = __halves2bfloat162(__float2bfloat16(ra), __float2bfloat16(rb));
    hi = *reinterpret_cast<uint32_t*>(&h);
    lo = *reinterpret_cast<uint32_t*>(&l);
}

__device__ __forceinline__ void ldsm_x4(uint32_t& r0, uint32_t& r1, uint32_t& r2, uint32_t& r3,
                                        uint32_t addr) {
    asm volatile("ldmatrix.sync.aligned.m8n8.x4.shared.b16 {%0,%1,%2,%3}, [%4];"
                 : "=r"(r0), "=r"(r1), "=r"(r2), "=r"(r3) : "r"(addr));
}

__device__ __forceinline__ void mma_bf16(float* c, const uint32_t* a, uint32_t b0, uint32_t b1) {
    asm volatile("mma.sync.aligned.m16n8k16.row.col.f32.bf16.bf16.f32 "
                 "{%0,%1,%2,%3}, {%4,%5,%6,%7}, {%8,%9}, {%0,%1,%2,%3};"
                 : "+f"(c[0]), "+f"(c[1]), "+f"(c[2]), "+f"(c[3])
                 : "r"(a[0]), "r"(a[1]), "r"(a[2]), "r"(a[3]), "r"(b0), "r"(b1));
}

#define CP_ASYNC16(dst, src) \
    asm volatile("cp.async.cg.shared.global [%0], [%1], 16;" :: "r"(dst), "l"(src) : "memory")
#define CP_COMMIT() asm volatile("cp.async.commit_group;" ::: "memory")

// ============================ kernels ============================
__global__ void init_kernel() {
    int t = threadIdx.x;
    if (t < KCODES) g_counts[t] = 0.0f;
    if (t == 0) { g_loss = 0.0; g_flag_cnt = 0; }
}

// One warp per code: pack [eh|el] bf16 + 0.5*||e||^2
__global__ void prep_kernel(const float* __restrict__ e) {
    int gw   = (blockIdx.x * blockDim.x + threadIdx.x) >> 5;
    int lane = threadIdx.x & 31;
    if (gw >= KCODES) return;
    const float4* er = (const float4*)(e + (size_t)gw * D);
    float4 a = er[lane * 2];
    float4 b = er[lane * 2 + 1];
    uint32_t h0,h1,h2,h3,l0,l1,l2,l3;
    split2(a.x, a.y, h0, l0);
    split2(a.z, a.w, h1, l1);
    split2(b.x, b.y, h2, l2);
    split2(b.z, b.w, h3, l3);
    *(uint4*)&g_epack[gw * 256 + lane * 4]       = make_uint4(h0, h1, h2, h3);
    *(uint4*)&g_epack[gw * 256 + 128 + lane * 4] = make_uint4(l0, l1, l2, l3);
    float s = a.x*a.x + a.y*a.y + a.z*a.z + a.w*a.w
            + b.x*b.x + b.y*b.y + b.z*b.z + b.w*b.w;
    #pragma unroll
    for (int o = 16; o > 0; o >>= 1) s += __shfl_down_sync(0xffffffffu, s, o);
    if (lane == 0) g_e_half[gw] = 0.5f * s;
}

// load one B tile (128 codes x 64 k' bf16 = 16KB) with XOR swizzle
__device__ __forceinline__ void load_B(uint32_t dstb, const char* src0, int tid) {
    #pragma unroll
    for (int it = 0; it < 4; ++it) {
        int i = it * 256 + tid;           // 16B units
        int r = i >> 3, s = i & 7;
        uint32_t ps = (uint32_t)s ^ ((uint32_t)r & 7u);
        CP_ASYNC16(dstb + (uint32_t)r * 128u + ps * 16u, src0 + (size_t)r * 1024 + s * 16);
    }
    CP_COMMIT();
}

#define UPD(sl, sval, scol) do { \
    float _s = (sval); \
    if (_s < m1s[sl]) { m2s[sl] = m1s[sl]; m1s[sl] = _s; i1s[sl] = (scol); } \
    else if (_s < m2s[sl]) m2s[sl] = _s; \
} while (0)

__global__ __launch_bounds__(256, 1) void vq_main(const float* __restrict__ z) {
    extern __shared__ char dsm[];
    char* base = (char*)(((uintptr_t)dsm + 1023) & ~(uintptr_t)1023);
    char*  sA   = base;                       // 131072 B : 128 rows x 512 bf16 (swizzled)
    char*  sB   = base + 131072;              // 2 x 16384 B
    float* s_eh = (float*)(base + 163840);    // 1024 f
    float* rm1  = (float*)(base + 167936);    // 128 x 2
    float* rm2  = (float*)(base + 168960);
    int*   rix  = (int*)  (base + 169984);

    const int tid  = threadIdx.x;
    const int lane = tid & 31;
    const int w    = tid >> 5;
    const int wm   = w >> 1;   // 0..3 : M warp (32 rows)
    const int wn   = w & 1;    // 0..1 : N warp (64 cols)
    const int rowbase = blockIdx.x * BM;
    const uint32_t sAu = smem_u32(sA);
    const uint32_t sBu = smem_u32(sB);

    for (int i = tid; i < KCODES; i += 256) s_eh[i] = g_e_half[i];

    // ---- convert this CTA's 128 z rows into swizzled bf16-pair SMEM A ----
    const float4* zb = (const float4*)(z + (size_t)rowbase * D);
    #pragma unroll
    for (int i = 0; i < 32; ++i) {
        int idx = i * 256 + tid;           // 8192 float4s
        int r = idx >> 6, f = idx & 63;    // f: float4 within row
        float4 v = zb[r * 64 + f];
        uint32_t h0, l0, h1, l1;
        split2(v.x, v.y, h0, l0);
        split2(v.z, v.w, h1, l1);
        int off8 = (f & 1) * 8;
        uint32_t segh = (uint32_t)(f >> 1);
        uint32_t segl = 32u + (uint32_t)(f >> 1);
        uint32_t ph = (segh & ~7u) | ((segh & 7u) ^ ((uint32_t)r & 7u));
        uint32_t pl = (segl & ~7u) | ((segl & 7u) ^ ((uint32_t)r & 7u));
        *(uint2*)(sA + (size_t)r * 1024 + ph * 16 + off8) = make_uint2(h0, h1);
        *(uint2*)(sA + (size_t)r * 1024 + pl * 16 + off8) = make_uint2(l0, l1);
    }
    __syncthreads();

    float m1s[4], m2s[4];
    int   i1s[4];
    #pragma unroll
    for (int s = 0; s < 4; ++s) { m1s[s] = __int_as_float(0x7f800000); m2s[s] = m1s[s]; i1s[s] = 0; }

    const char* eb = (const char*)g_epack;

    #pragma unroll 1
    for (int nt = 0; nt < 8; ++nt) {
        float acc[2][4][2][4];
        #pragma unroll
        for (int a = 0; a < 2; ++a)
            #pragma unroll
            for (int p = 0; p < 4; ++p)
                #pragma unroll
                for (int g = 0; g < 2; ++g)
                    #pragma unroll
                    for (int e = 0; e < 4; ++e) acc[a][p][g][e] = 0.0f;

        const char* ebase = eb + (size_t)nt * 128 * 1024;
        load_B(sBu, ebase, tid);                       // chunk 0 -> buf 0

        #pragma unroll 1
        for (int c = 0; c < 8; ++c) {
            if (c < 7) {
                load_B(sBu + (uint32_t)((c + 1) & 1) * 16384u, ebase + (c + 1) * 128, tid);
                asm volatile("cp.async.wait_group 1;" ::: "memory");
            } else {
                asm volatile("cp.async.wait_group 0;" ::: "memory");
            }
            __syncthreads();
            uint32_t bufo = (uint32_t)(c & 1) * 16384u;

            #pragma unroll
            for (int ks = 0; ks < 4; ++ks) {
                // B fragments for this k-slice (reused by both A pairings)
                uint32_t bfr[4][4];
                #pragma unroll
                for (int p = 0; p < 4; ++p) {
                    int br = wn * 64 + p * 16 + (lane & 7) + ((lane >> 4) & 1) * 8;
                    uint32_t ls = (uint32_t)(ks * 2) + (uint32_t)((lane >> 3) & 1);
                    uint32_t ps = ls ^ ((uint32_t)br & 7u);
                    ldsm_x4(bfr[p][0], bfr[p][1], bfr[p][2], bfr[p][3],
                            sBu + bufo + (uint32_t)br * 128u + ps * 16u);
                }
                // pairing 0: A chunk c   (zh*eh for c<4, zl*el for c>=4)
                // pairing 1: A chunk c^4 (zl*eh for c<4, zh*el for c>=4)
                #pragma unroll
                for (int pr = 0; pr < 2; ++pr) {
                    int ac = pr ? (c ^ 4) : c;
                    uint32_t kbyte = (uint32_t)(ac * 128 + ks * 32);
                    uint32_t afr[2][4];
                    #pragma unroll
                    for (int mf = 0; mf < 2; ++mf) {
                        int ar = wm * 32 + mf * 16 + (lane & 15);
                        uint32_t seg = (kbyte >> 4) + (uint32_t)(lane >> 4);
                        uint32_t ps = (seg & ~7u) | ((seg & 7u) ^ ((uint32_t)ar & 7u));
                        ldsm_x4(afr[mf][0], afr[mf][1], afr[mf][2], afr[mf][3],
                                sAu + (uint32_t)ar * 1024u + ps * 16u);
                    }
                    #pragma unroll
                    for (int p = 0; p < 4; ++p) {
                        mma_bf16(acc[0][p][0], afr[0], bfr[p][0], bfr[p][1]);
                        mma_bf16(acc[0][p][1], afr[0], bfr[p][2], bfr[p][3]);
                        mma_bf16(acc[1][p][0], afr[1], bfr[p][0], bfr[p][1]);
                        mma_bf16(acc[1][p][1], afr[1], bfr[p][2], bfr[p][3]);
                    }
                }
            }
            __syncthreads();
        }

        // epilogue: score = 0.5||e||^2 - dot ; update running (m1, m2, idx)
        int ntb = nt * 128 + wn * 64;
        #pragma unroll
        for (int mf = 0; mf < 2; ++mf)
            #pragma unroll
            for (int p = 0; p < 4; ++p)
                #pragma unroll
                for (int g = 0; g < 2; ++g) {
                    int colb = ntb + p * 16 + g * 8 + (lane & 3) * 2;
                    float e0 = s_eh[colb], e1 = s_eh[colb + 1];
                    UPD(mf * 2 + 0, e0 - acc[mf][p][g][0], colb);
                    UPD(mf * 2 + 0, e1 - acc[mf][p][g][1], colb + 1);
                    UPD(mf * 2 + 1, e0 - acc[mf][p][g][2], colb);
                    UPD(mf * 2 + 1, e1 - acc[mf][p][g][3], colb + 1);
                }
    }

    // ---- reduce across the 4 lanes sharing each row ----
    #pragma unroll
    for (int sl = 0; sl < 4; ++sl) {
        float m1 = m1s[sl], m2 = m2s[sl];
        int i1 = i1s[sl];
        #pragma unroll
        for (int o = 1; o <= 2; o <<= 1) {
            float om1 = __shfl_xor_sync(0xffffffffu, m1, o);
            float om2 = __shfl_xor_sync(0xffffffffu, m2, o);
            int   oi1 = __shfl_xor_sync(0xffffffffu, i1, o);
            float nm2 = fminf(fminf(m2, om2), fmaxf(m1, om1));
            if (om1 < m1 || (om1 == m1 && oi1 < i1)) { m1 = om1; i1 = oi1; }
            m2 = nm2;
        }
        if ((lane & 3) == 0) {
            int row = wm * 32 + (sl >> 1) * 16 + (sl & 1) * 8 + (lane >> 2);
            rm1[row * 2 + wn] = m1;
            rm2[row * 2 + wn] = m2;
            rix[row * 2 + wn] = i1;
        }
    }
    __syncthreads();

    if (tid < BM) {
        float a1 = rm1[tid * 2], b1 = rm1[tid * 2 + 1];
        float a2 = rm2[tid * 2], b2 = rm2[tid * 2 + 1];
        int   ai = rix[tid * 2], bi = rix[tid * 2 + 1];
        float m1; int i1;
        if (b1 < a1 || (b1 == a1 && bi < ai)) { m1 = b1; i1 = bi; }
        else                                  { m1 = a1; i1 = ai; }
        float m2 = fminf(fminf(a2, b2), fmaxf(a1, b1));
        g_idx[rowbase + tid] = i1;
        if (m2 - m1 < GAP_THRESH) {
            int p = atomicAdd(&g_flag_cnt, 1);
            g_flag_rows[p] = rowbase + tid;
        }
    }
}

// exact fp32 re-argmin for flagged rows
__global__ __launch_bounds__(256) void rescue_kernel(const float* __restrict__ z,
                                                     const float* __restrict__ e) {
    __shared__ float4 zs[64];
    __shared__ float rv[8];
    __shared__ int   rixs[8];
    int cnt = g_flag_cnt;
    int tid = threadIdx.x, wid = tid >> 5, lane = tid & 31;
    for (int ri = blockIdx.x; ri < cnt; ri += gridDim.x) {
        int row = g_flag_rows[ri];
        if (tid < 64) zs[tid] = ((const float4*)(z + (size_t)row * D))[tid];
        __syncthreads();
        float bm = __int_as_float(0x7f800000);
        int   bi = 0;
        for (int c = wid; c < KCODES; c += 8) {
            const float4* er = (const float4*)(e + (size_t)c * D);
            float acc = 0.0f;
            #pragma unroll
            for (int i = 0; i < 2; ++i) {
                float4 ev = er[lane + 32 * i];
                float4 zv = zs[lane + 32 * i];
                acc += ev.x*zv.x + ev.y*zv.y + ev.z*zv.z + ev.w*zv.w;
            }
            #pragma unroll
            for (int o = 16; o > 0; o >>= 1) acc += __shfl_down_sync(0xffffffffu, acc, o);
            if (lane == 0) {
                float s = g_e_half[c] - acc;
                if (s < bm || (s == bm && c < bi)) { bm = s; bi = c; }
            }
        }
        if (lane == 0) { rv[wid] = bm; rixs[wid] = bi; }
        __syncthreads();
        if (tid == 0) {
            float bv = rv[0]; int bb = rixs[0];
            #pragma unroll
            for (int w = 1; w < 8; ++w)
                if (rv[w] < bv || (rv[w] == bv && rixs[w] < bb)) { bv = rv[w]; bb = rixs[w]; }
            g_idx[row] = bb;
        }
        __syncthreads();
    }
}

// gather quantized rows, exact loss, counts
__global__ __launch_bounds__(256) void output_kernel(const float* __restrict__ z,
                                                     const float* __restrict__ e,
                                                     float* __restrict__ outq) {
    __shared__ int s_idx[BM];
    __shared__ float red[256];
    int tid = threadIdx.x;
    int rowbase = blockIdx.x * BM;
    if (tid < BM) {
        int ix = g_idx[rowbase + tid];
        s_idx[tid] = ix;
        atomicAdd(&g_counts[ix], 1.0f);
    }
    __syncthreads();
    float acc = 0.0f;
    #pragma unroll 4
    for (int p = tid; p < BM * D; p += 256) {
        int r = p >> 8;
        int c = p & 255;
        float q  = e[(size_t)s_idx[r] * D + c];
        float zv = z[(size_t)(rowbase + r) * D + c];
        outq[(size_t)(rowbase + r) * D + c] = q;
        float d = q - zv;
        acc += d * d;
    }
    red[tid] = acc;
    __syncthreads();
    for (int o = 128; o > 32; o >>= 1) {
        if (tid < o) red[tid] += red[tid + o];
        __syncthreads();
    }
    if (tid < 32) {
        float v = red[tid] + red[tid + 32];
        #pragma unroll
        for (int o = 16; o > 0; o >>= 1) v += __shfl_down_sync(0xffffffffu, v, o);
        if (tid == 0) atomicAdd(&g_loss, (double)v);
    }
}

__global__ void finalize_kernel(float* __restrict__ out, int N) {
    __shared__ float red[1024];
    int t = threadIdx.x;
    float p = g_counts[t] * (1.0f / (float)N);
    red[t] = p * logf(p + 1e-10f);
    __syncthreads();
    for (int o = 512; o > 0; o >>= 1) {
        if (t < o) red[t] += red[t + o];
        __syncthreads();
    }
    if (t == 0) {
        out[0] = 0.25f * (float)(g_loss / ((double)N * (double)D));
        out[(size_t)N * D + 1] = expf(-red[0]);
    }
}

// ---------------------------------------------------------------------------
extern "C" void kernel_launch(void* const* d_in, const int* in_sizes, int n_in,
                              void* d_out, int out_size) {
    const float* z = (const float*)d_in[0];   // z_e  [N, 256]
    const float* e = (const float*)d_in[1];   // emb  [1024, 256]
    float* out = (float*)d_out;               // [loss, quantized(N*256), perplexity]
    int N = in_sizes[0] / D;                  // 131072

    cudaFuncSetAttribute(vq_main, cudaFuncAttributeMaxDynamicSharedMemorySize, DYN_SMEM);

    init_kernel<<<1, 1024>>>();
    prep_kernel<<<(KCODES * 32) / 256, 256>>>(e);
    vq_main<<<N / BM, 256, DYN_SMEM>>>(z);
    rescue_kernel<<<256, 256>>>(z, e);
    output_kernel<<<N / BM, 256>>>(z, e, out + 1);
    finalize_kernel<<<1, 1024>>>(out, N);
}

// round 6
// speedup vs baseline: 2.0604x; 1.0409x over previous
#include <cuda_runtime.h>
#include <cuda_bf16.h>
#include <cstdint>

#define D        256
#define KCODES   1024
#define BM       128
#define GAP_THRESH 0.001f
// sA 128KB + sB 4x16KB + eh 4KB + reduce arrays + pad
#define DYN_SMEM 205824

// ---- device scratch (no allocations allowed) ----
__device__ uint32_t g_epack[KCODES * 256];   // per code: [eh 128 u32 | el 128 u32] (bf16x2)
__device__ float    g_e_half[KCODES];
__device__ float    g_counts[KCODES];
__device__ int      g_flag_rows[131072];
__device__ int      g_flag_cnt;
__device__ double   g_loss;

// ============================ helpers ============================
__device__ __forceinline__ uint32_t smem_u32(const void* p) {
    uint32_t a;
    asm("{ .reg .u64 t; cvta.to.shared.u64 t, %1; cvt.u32.u64 %0, t; }" : "=r"(a) : "l"(p));
    return a;
}

__device__ __forceinline__ void split2(float a, float b, uint32_t& hi, uint32_t& lo) {
    __nv_bfloat16 ha = __float2bfloat16(a);
    __nv_bfloat16 hb = __float2bfloat16(b);
    float ra = a - __bfloat162float(ha);
    float rb = b - __bfloat162float(hb);
    __nv_bfloat162 h = __halves2bfloat162(ha, hb);
    __nv_bfloat162 l = __halves2bfloat162(__float2bfloat16(ra), __float2bfloat16(rb));
    hi = *reinterpret_cast<uint32_t*>(&h);
    lo = *reinterpret_cast<uint32_t*>(&l);
}

__device__ __forceinline__ void ldsm_x4(uint32_t& r0, uint32_t& r1, uint32_t& r2, uint32_t& r3,
                                        uint32_t addr) {
    asm volatile("ldmatrix.sync.aligned.m8n8.x4.shared.b16 {%0,%1,%2,%3}, [%4];"
                 : "=r"(r0), "=r"(r1), "=r"(r2), "=r"(r3) : "r"(addr));
}

__device__ __forceinline__ void mma_bf16(float* c, const uint32_t* a, uint32_t b0, uint32_t b1) {
    asm volatile("mma.sync.aligned.m16n8k16.row.col.f32.bf16.bf16.f32 "
                 "{%0,%1,%2,%3}, {%4,%5,%6,%7}, {%8,%9}, {%0,%1,%2,%3};"
                 : "+f"(c[0]), "+f"(c[1]), "+f"(c[2]), "+f"(c[3])
                 : "r"(a[0]), "r"(a[1]), "r"(a[2]), "r"(a[3]), "r"(b0), "r"(b1));
}

#define CP_ASYNC16(dst, src) \
    asm volatile("cp.async.cg.shared.global [%0], [%1], 16;" :: "r"(dst), "l"(src) : "memory")
#define CP_COMMIT() asm volatile("cp.async.commit_group;" ::: "memory")

// ============================ kernels ============================
// One warp per code: pack [eh|el] bf16 + 0.5*||e||^2 ; also reset globals
__global__ void prep_kernel(const float* __restrict__ e) {
    int tid  = threadIdx.x;
    int gw   = (blockIdx.x * blockDim.x + tid) >> 5;
    int lane = tid & 31;
    if (blockIdx.x < 4) g_counts[blockIdx.x * 256 + tid] = 0.0f;
    if (blockIdx.x == 0 && tid == 0) { g_loss = 0.0; g_flag_cnt = 0; }
    if (gw >= KCODES) return;
    const float4* er = (const float4*)(e + (size_t)gw * D);
    float4 a = er[lane * 2];
    float4 b = er[lane * 2 + 1];
    uint32_t h0,h1,h2,h3,l0,l1,l2,l3;
    split2(a.x, a.y, h0, l0);
    split2(a.z, a.w, h1, l1);
    split2(b.x, b.y, h2, l2);
    split2(b.z, b.w, h3, l3);
    *(uint4*)&g_epack[gw * 256 + lane * 4]       = make_uint4(h0, h1, h2, h3);
    *(uint4*)&g_epack[gw * 256 + 128 + lane * 4] = make_uint4(l0, l1, l2, l3);
    float s = a.x*a.x + a.y*a.y + a.z*a.z + a.w*a.w
            + b.x*b.x + b.y*b.y + b.z*b.z + b.w*b.w;
    #pragma unroll
    for (int o = 16; o > 0; o >>= 1) s += __shfl_down_sync(0xffffffffu, s, o);
    if (lane == 0) g_e_half[gw] = 0.5f * s;
}

// load one B chunk (128 codes x 64 k' bf16 = 16KB) with XOR swizzle; one cp.async group
__device__ __forceinline__ void load_chunk(uint32_t dstb, int g, int tid) {
    const char* src0 = (const char*)g_epack + (size_t)(g >> 3) * 131072 + (size_t)(g & 7) * 128;
    #pragma unroll
    for (int it = 0; it < 4; ++it) {
        int i = it * 256 + tid;           // 16B units
        int r = i >> 3, s = i & 7;
        uint32_t ps = (uint32_t)s ^ ((uint32_t)r & 7u);
        CP_ASYNC16(dstb + (uint32_t)r * 128u + ps * 16u, src0 + (size_t)r * 1024 + s * 16);
    }
    CP_COMMIT();
}

#define UPD(sl, sval, scol) do { \
    float _s = (sval); \
    if (_s < m1s[sl]) { m2s[sl] = m1s[sl]; m1s[sl] = _s; i1s[sl] = (scol); } \
    else if (_s < m2s[sl]) m2s[sl] = _s; \
} while (0)

__global__ __launch_bounds__(256, 1) void vq_main(const float* __restrict__ z,
                                                  const float* __restrict__ e,
                                                  float* __restrict__ outq) {
    extern __shared__ char dsm[];
    char* base = (char*)(((uintptr_t)dsm + 1023) & ~(uintptr_t)1023);
    char*  sA   = base;                       // 131072 : 128 rows x 512 bf16 (swizzled)
    char*  sB   = base + 131072;              // 4 x 16384
    float* s_eh = (float*)(base + 196608);    // 1024 f
    float* rm1  = (float*)(base + 200704);    // 128 x 2
    float* rm2  = (float*)(base + 201728);
    int*   rix  = (int*)  (base + 202752);
    int*   sidx = (int*)  (base + 203776);    // 128
    int*   sflg = (int*)  (base + 204288);    // 128

    const int tid  = threadIdx.x;
    const int lane = tid & 31;
    const int w    = tid >> 5;
    const int wm   = w >> 1;   // 0..3 : M warp (32 rows)
    const int wn   = w & 1;    // 0..1 : N warp (64 cols)
    const int rowbase = blockIdx.x * BM;
    const uint32_t sAu = smem_u32(sA);
    const uint32_t sBu = smem_u32(sB);

    // issue first 3 B chunks before the A conversion (overlap)
    load_chunk(sBu,          0, tid);
    load_chunk(sBu + 16384u, 1, tid);
    load_chunk(sBu + 32768u, 2, tid);

    for (int i = tid; i < KCODES; i += 256) s_eh[i] = g_e_half[i];

    // ---- convert this CTA's 128 z rows into swizzled bf16-pair SMEM A ----
    const float4* zb = (const float4*)(z + (size_t)rowbase * D);
    #pragma unroll
    for (int i = 0; i < 32; ++i) {
        int idx = i * 256 + tid;           // 8192 float4s
        int r = idx >> 6, f = idx & 63;
        float4 v = zb[r * 64 + f];
        uint32_t h0, l0, h1, l1;
        split2(v.x, v.y, h0, l0);
        split2(v.z, v.w, h1, l1);
        int off8 = (f & 1) * 8;
        uint32_t segh = (uint32_t)(f >> 1);
        uint32_t segl = 32u + (uint32_t)(f >> 1);
        uint32_t ph = (segh & ~7u) | ((segh & 7u) ^ ((uint32_t)r & 7u));
        uint32_t pl = (segl & ~7u) | ((segl & 7u) ^ ((uint32_t)r & 7u));
        *(uint2*)(sA + (size_t)r * 1024 + ph * 16 + off8) = make_uint2(h0, h1);
        *(uint2*)(sA + (size_t)r * 1024 + pl * 16 + off8) = make_uint2(l0, l1);
    }

    float m1s[4], m2s[4];
    int   i1s[4];
    #pragma unroll
    for (int s = 0; s < 4; ++s) { m1s[s] = __int_as_float(0x7f800000); m2s[s] = m1s[s]; i1s[s] = 0; }

    float acc[2][4][2][4];

    // ---- continuous pipeline over 64 B chunks (8 nt x 8 c), one sync per chunk ----
    #pragma unroll 1
    for (int g = 0; g < 64; ++g) {
        int c = g & 7;
        if (c == 0) {
            #pragma unroll
            for (int a = 0; a < 2; ++a)
                #pragma unroll
                for (int p = 0; p < 4; ++p)
                    #pragma unroll
                    for (int q = 0; q < 2; ++q)
                        #pragma unroll
                        for (int x = 0; x < 4; ++x) acc[a][p][q][x] = 0.0f;
        }
        if (g < 62)      asm volatile("cp.async.wait_group 2;" ::: "memory");
        else if (g == 62) asm volatile("cp.async.wait_group 1;" ::: "memory");
        else              asm volatile("cp.async.wait_group 0;" ::: "memory");
        __syncthreads();   // chunk g visible to all; all warps done with buf (g-1)&3
        if (g + 3 < 64) load_chunk(sBu + (uint32_t)((g + 3) & 3) * 16384u, g + 3, tid);

        uint32_t bufo = (uint32_t)(g & 3) * 16384u;
        int npr = (c < 4) ? 2 : 1;

        #pragma unroll
        for (int ks = 0; ks < 4; ++ks) {
            uint32_t bfr[4][4];
            #pragma unroll
            for (int p = 0; p < 4; ++p) {
                int br = wn * 64 + p * 16 + (lane & 7) + ((lane >> 4) & 1) * 8;
                uint32_t ls = (uint32_t)(ks * 2) + (uint32_t)((lane >> 3) & 1);
                uint32_t ps = ls ^ ((uint32_t)br & 7u);
                ldsm_x4(bfr[p][0], bfr[p][1], bfr[p][2], bfr[p][3],
                        sBu + bufo + (uint32_t)br * 128u + ps * 16u);
            }
            // 3-term: c<4 (B=eh): A = {zh(c), zl(c+4)} ; c>=4 (B=el): A = {zh(c-4)}
            #pragma unroll
            for (int pr = 0; pr < 2; ++pr) {
                if (pr >= npr) break;
                int ac = (c < 4) ? (pr ? c + 4 : c) : (c - 4);
                uint32_t kbyte = (uint32_t)(ac * 128 + ks * 32);
                uint32_t afr[2][4];
                #pragma unroll
                for (int mf = 0; mf < 2; ++mf) {
                    int ar = wm * 32 + mf * 16 + (lane & 15);
                    uint32_t seg = (kbyte >> 4) + (uint32_t)(lane >> 4);
                    uint32_t ps = (seg & ~7u) | ((seg & 7u) ^ ((uint32_t)ar & 7u));
                    ldsm_x4(afr[mf][0], afr[mf][1], afr[mf][2], afr[mf][3],
                            sAu + (uint32_t)ar * 1024u + ps * 16u);
                }
                #pragma unroll
                for (int p = 0; p < 4; ++p) {
                    mma_bf16(acc[0][p][0], afr[0], bfr[p][0], bfr[p][1]);
                    mma_bf16(acc[0][p][1], afr[0], bfr[p][2], bfr[p][3]);
                    mma_bf16(acc[1][p][0], afr[1], bfr[p][0], bfr[p][1]);
                    mma_bf16(acc[1][p][1], afr[1], bfr[p][2], bfr[p][3]);
                }
            }
        }

        if (c == 7) {
            // epilogue for this nt: score = 0.5||e||^2 - dot
            int ntb = (g >> 3) * 128 + wn * 64;
            #pragma unroll
            for (int mf = 0; mf < 2; ++mf)
                #pragma unroll
                for (int p = 0; p < 4; ++p)
                    #pragma unroll
                    for (int q = 0; q < 2; ++q) {
                        int colb = ntb + p * 16 + q * 8 + (lane & 3) * 2;
                        float e0 = s_eh[colb], e1 = s_eh[colb + 1];
                        UPD(mf * 2 + 0, e0 - acc[mf][p][q][0], colb);
                        UPD(mf * 2 + 0, e1 - acc[mf][p][q][1], colb + 1);
                        UPD(mf * 2 + 1, e0 - acc[mf][p][q][2], colb);
                        UPD(mf * 2 + 1, e1 - acc[mf][p][q][3], colb + 1);
                    }
        }
    }

    // ---- reduce across the 4 lanes sharing each row ----
    #pragma unroll
    for (int sl = 0; sl < 4; ++sl) {
        float m1 = m1s[sl], m2 = m2s[sl];
        int i1 = i1s[sl];
        #pragma unroll
        for (int o = 1; o <= 2; o <<= 1) {
            float om1 = __shfl_xor_sync(0xffffffffu, m1, o);
            float om2 = __shfl_xor_sync(0xffffffffu, m2, o);
            int   oi1 = __shfl_xor_sync(0xffffffffu, i1, o);
            float nm2 = fminf(fminf(m2, om2), fmaxf(m1, om1));
            if (om1 < m1 || (om1 == m1 && oi1 < i1)) { m1 = om1; i1 = oi1; }
            m2 = nm2;
        }
        if ((lane & 3) == 0) {
            int row = wm * 32 + (sl >> 1) * 16 + (sl & 1) * 8 + (lane >> 2);
            rm1[row * 2 + wn] = m1;
            rm2[row * 2 + wn] = m2;
            rix[row * 2 + wn] = i1;
        }
    }
    __syncthreads();

    if (tid < BM) {
        float a1 = rm1[tid * 2], b1 = rm1[tid * 2 + 1];
        float a2 = rm2[tid * 2], b2 = rm2[tid * 2 + 1];
        int   ai = rix[tid * 2], bi = rix[tid * 2 + 1];
        float m1; int i1;
        if (b1 < a1 || (b1 == a1 && bi < ai)) { m1 = b1; i1 = bi; }
        else                                  { m1 = a1; i1 = ai; }
        float m2 = fminf(fminf(a2, b2), fmaxf(a1, b1));
        sidx[tid] = i1;
        int fl = (m2 - m1 < GAP_THRESH) ? 1 : 0;
        sflg[tid] = fl;
        if (fl) {
            int p = atomicAdd(&g_flag_cnt, 1);
            g_flag_rows[p] = rowbase + tid;
        } else {
            atomicAdd(&g_counts[i1], 1.0f);
        }
    }
    __syncthreads();

    // ---- fused output: gather + loss for non-flagged rows ----
    float lacc = 0.0f;
    #pragma unroll 4
    for (int p = tid; p < BM * D; p += 256) {
        int r = p >> 8;
        int cc = p & 255;
        if (!sflg[r]) {
            float q  = e[(size_t)sidx[r] * D + cc];
            float zv = z[(size_t)(rowbase + r) * D + cc];
            outq[(size_t)(rowbase + r) * D + cc] = q;
            float d = q - zv;
            lacc += d * d;
        }
    }
    float* red = rm1;   // reuse (256 floats span rm1+rm2)
    red[tid] = lacc;
    __syncthreads();
    for (int o = 128; o > 32; o >>= 1) {
        if (tid < o) red[tid] += red[tid + o];
        __syncthreads();
    }
    if (tid < 32) {
        float v = red[tid] + red[tid + 32];
        #pragma unroll
        for (int o = 16; o > 0; o >>= 1) v += __shfl_down_sync(0xffffffffu, v, o);
        if (tid == 0) atomicAdd(&g_loss, (double)v);
    }
}

// exact fp32 re-argmin + output for flagged rows. block-per-row, warp-per-code.
__global__ __launch_bounds__(256) void rescue_kernel(const float* __restrict__ z,
                                                     const float* __restrict__ e,
                                                     float* __restrict__ outq) {
    __shared__ float zs[256];
    __shared__ float rbv[8];
    __shared__ int   rbi[8];
    __shared__ int   s_best;
    __shared__ float red[256];
    int cnt = g_flag_cnt;
    int tid = threadIdx.x, w = tid >> 5, lane = tid & 31;
    for (int ri = blockIdx.x; ri < cnt; ri += gridDim.x) {
        int row = g_flag_rows[ri];
        if (tid < 64) ((float4*)zs)[tid] = ((const float4*)(z + (size_t)row * D))[tid];
        __syncthreads();
        float4 za = ((const float4*)zs)[lane];
        float4 zc = ((const float4*)zs)[lane + 32];

        float bm = __int_as_float(0x7f800000);
        int   bi = KCODES;
        int wbase = w * 128;
        #pragma unroll 1
        for (int k = 0; k < 128; k += 2) {
            int c0 = wbase + k, c1 = c0 + 1;
            const float4* e0 = (const float4*)(e + (size_t)c0 * D);
            const float4* e1 = (const float4*)(e + (size_t)c1 * D);
            float4 a0 = e0[lane], b0 = e0[lane + 32];
            float4 a1 = e1[lane], b1 = e1[lane + 32];
            float d0 = a0.x*za.x + a0.y*za.y + a0.z*za.z + a0.w*za.w
                     + b0.x*zc.x + b0.y*zc.y + b0.z*zc.z + b0.w*zc.w;
            float d1 = a1.x*za.x + a1.y*za.y + a1.z*za.z + a1.w*za.w
                     + b1.x*zc.x + b1.y*zc.y + b1.z*zc.z + b1.w*zc.w;
            #pragma unroll
            for (int o = 16; o > 0; o >>= 1) {
                d0 += __shfl_xor_sync(0xffffffffu, d0, o);
                d1 += __shfl_xor_sync(0xffffffffu, d1, o);
            }
            float s0 = g_e_half[c0] - d0;
            float s1 = g_e_half[c1] - d1;
            if (s0 < bm) { bm = s0; bi = c0; }
            if (s1 < bm) { bm = s1; bi = c1; }
        }
        if (lane == 0) { rbv[w] = bm; rbi[w] = bi; }
        __syncthreads();
        if (tid == 0) {
            float bv = rbv[0]; int bb = rbi[0];
            #pragma unroll
            for (int j = 1; j < 8; ++j)
                if (rbv[j] < bv || (rbv[j] == bv && rbi[j] < bb)) { bv = rbv[j]; bb = rbi[j]; }
            s_best = bb;
            atomicAdd(&g_counts[bb], 1.0f);
        }
        __syncthreads();
        int best = s_best;
        float q  = e[(size_t)best * D + tid];
        float dv = q - zs[tid];
        outq[(size_t)row * D + tid] = q;
        red[tid] = dv * dv;
        __syncthreads();
        for (int o = 128; o > 32; o >>= 1) {
            if (tid < o) red[tid] += red[tid + o];
            __syncthreads();
        }
        if (tid < 32) {
            float v = red[tid] + red[tid + 32];
            #pragma unroll
            for (int o = 16; o > 0; o >>= 1) v += __shfl_down_sync(0xffffffffu, v, o);
            if (tid == 0) atomicAdd(&g_loss, (double)v);
        }
        __syncthreads();
    }
}

__global__ void finalize_kernel(float* __restrict__ out, int N) {
    __shared__ float red[1024];
    int t = threadIdx.x;
    float p = g_counts[t] * (1.0f / (float)N);
    red[t] = p * logf(p + 1e-10f);
    __syncthreads();
    for (int o = 512; o > 0; o >>= 1) {
        if (t < o) red[t] += red[t + o];
        __syncthreads();
    }
    if (t == 0) {
        out[0] = 0.25f * (float)(g_loss / ((double)N * (double)D));
        out[(size_t)N * D + 1] = expf(-red[0]);
    }
}

// ---------------------------------------------------------------------------
extern "C" void kernel_launch(void* const* d_in, const int* in_sizes, int n_in,
                              void* d_out, int out_size) {
    const float* z = (const float*)d_in[0];   // z_e  [N, 256]
    const float* e = (const float*)d_in[1];   // emb  [1024, 256]
    float* out = (float*)d_out;               // [loss, quantized(N*256), perplexity]
    int N = in_sizes[0] / D;                  // 131072

    cudaFuncSetAttribute(vq_main, cudaFuncAttributeMaxDynamicSharedMemorySize, DYN_SMEM);

    prep_kernel<<<(KCODES * 32) / 256, 256>>>(e);
    vq_main<<<N / BM, 256, DYN_SMEM>>>(z, e, out + 1);
    rescue_kernel<<<512, 256>>>(z, e, out + 1);
    finalize_kernel<<<1, 1024>>>(out, N);
}